// round 7
// baseline (speedup 1.0000x reference)
#include <cuda_runtime.h>
#include <cstdint>

// Problem constants (fixed by the reference setup_inputs)
#define BATCH 2
#define SEQ   2048
#define DMODEL 1024
#define NHEAD 16
#define DK    64
#define MROWS (BATCH * SEQ)   // 4096

// Scratch: Q,K,V in [B,H,S,DK] (tf32-rounded floats), O in [B,S,D]
__device__ float g_Q[BATCH * NHEAD * SEQ * DK];
__device__ float g_K[BATCH * NHEAD * SEQ * DK];
__device__ float g_V[BATCH * NHEAD * SEQ * DK];
__device__ float g_O[BATCH * SEQ * DMODEL];

// ---------------------------------------------------------------------------
// helpers
// ---------------------------------------------------------------------------
__device__ __forceinline__ unsigned f2tf32(float f) {
    unsigned u;
    asm("cvt.rna.tf32.f32 %0, %1;" : "=r"(u) : "f"(f));
    return u;
}

__device__ __forceinline__ void mma_tf32(float c[4], const unsigned a[4], const unsigned b[2]) {
    asm volatile(
        "mma.sync.aligned.m16n8k8.row.col.f32.tf32.tf32.f32 "
        "{%0,%1,%2,%3}, {%4,%5,%6,%7}, {%8,%9}, {%0,%1,%2,%3};\n"
        : "+f"(c[0]), "+f"(c[1]), "+f"(c[2]), "+f"(c[3])
        : "r"(a[0]), "r"(a[1]), "r"(a[2]), "r"(a[3]), "r"(b[0]), "r"(b[1]));
}

__device__ __forceinline__ void mma_bf16(float c[4], const unsigned a[4], const unsigned b[2]) {
    asm volatile(
        "mma.sync.aligned.m16n8k16.row.col.f32.bf16.bf16.f32 "
        "{%0,%1,%2,%3}, {%4,%5,%6,%7}, {%8,%9}, {%0,%1,%2,%3};\n"
        : "+f"(c[0]), "+f"(c[1]), "+f"(c[2]), "+f"(c[3])
        : "r"(a[0]), "r"(a[1]), "r"(a[2]), "r"(a[3]), "r"(b[0]), "r"(b[1]));
}

// pack two floats into bf16x2: lo half = f0, hi half = f1
__device__ __forceinline__ unsigned pack_bf16x2(float f0, float f1) {
    unsigned r;
    asm("cvt.rn.bf16x2.f32 %0, %1, %2;" : "=r"(r) : "f"(f1), "f"(f0));
    return r;
}

#define CP_ASYNC16(dst_u32, src) \
    asm volatile("cp.async.cg.shared.global [%0], [%1], 16;" :: "r"(dst_u32), "l"(src))
#define CP_COMMIT() asm volatile("cp.async.commit_group;")
#define CP_WAIT1()  asm volatile("cp.async.wait_group 1;")

// ---------------------------------------------------------------------------
// Tensor-core GEMM core, bf16x3 compensated:
//   a = a_hi + a_lo (bf16 split); C = a_hi*b_hi + a_lo*b_hi + a_hi*b_lo
//   (dropped a_lo*b_lo term ~ 2^-18 relative -> near-fp32 accuracy)
// C[M,N] = A[M,K] @ W[N,K]^T.  M=4096, N=1024, K=1024.
// CTA 128x128, K-chunk 16 (one m16n8k16 step), 8 warps (4M x 2N).
// smem rows: 8 bf16x2 words (+4 pad) -> frag bank (12g+tg)%32 bijective.
// ---------------------------------------------------------------------------
#define GPAD 12

struct GemmSmem {
    unsigned Ah[128][GPAD];
    unsigned Al[128][GPAD];
    unsigned Wh[128][GPAD];
    unsigned Wl[128][GPAD];
};

__device__ __forceinline__ void split_store(
    unsigned (&hiArr)[128][GPAD], unsigned (&loArr)[128][GPAD],
    int row, int w4, const float4& v0, const float4& v1)
{
    const float f[8] = {v0.x, v0.y, v0.z, v0.w, v1.x, v1.y, v1.z, v1.w};
    uint4 hi, lo;
    unsigned* hw = (unsigned*)&hi;
    unsigned* lw = (unsigned*)&lo;
#pragma unroll
    for (int j = 0; j < 4; j++) {
        unsigned w = pack_bf16x2(f[2 * j], f[2 * j + 1]);
        hw[j] = w;
        float h0 = __uint_as_float((w & 0xffffu) << 16);
        float h1 = __uint_as_float(w & 0xffff0000u);
        lw[j] = pack_bf16x2(f[2 * j] - h0, f[2 * j + 1] - h1);
    }
    *(uint4*)&hiArr[row][w4] = hi;
    *(uint4*)&loArr[row][w4] = lo;
}

// Computes the accumulators for this CTA; caller handles the epilogue.
__device__ __forceinline__ void gemm_core(
    const float* __restrict__ Ap, const float* __restrict__ W,
    int m0, int n0, float acc[2][8][4])
{
    __shared__ GemmSmem sm;

    const int tid  = threadIdx.x;
    const int warp = tid >> 5;
    const int lane = tid & 31;
    const int g    = lane >> 2;
    const int tg   = lane & 3;
    const int wm   = warp >> 1;
    const int wn   = warp & 1;

    // loader: one row per thread, k-half h (8 floats = 2 float4 per matrix)
    const int lrow = tid & 127;
    const int lh   = tid >> 7;          // 0 or 1
    const int lk   = lh << 3;           // float offset 0 or 8
    const int lw4  = lh << 2;           // word offset 0 or 4

#pragma unroll
    for (int mf = 0; mf < 2; mf++)
#pragma unroll
        for (int nf = 0; nf < 8; nf++)
#pragma unroll
            for (int j = 0; j < 4; j++) acc[mf][nf][j] = 0.f;

    float4 aR0, aR1, wR0, wR1;
    aR0 = *(const float4*)&Ap[(m0 + lrow) * DMODEL + lk];
    aR1 = *(const float4*)&Ap[(m0 + lrow) * DMODEL + lk + 4];
    wR0 = *(const float4*)&W[(n0 + lrow) * DMODEL + lk];
    wR1 = *(const float4*)&W[(n0 + lrow) * DMODEL + lk + 4];

    for (int k0 = 0; k0 < DMODEL; k0 += 16) {
        __syncthreads();
        split_store(sm.Ah, sm.Al, lrow, lw4, aR0, aR1);
        split_store(sm.Wh, sm.Wl, lrow, lw4, wR0, wR1);
        __syncthreads();

        if (k0 + 16 < DMODEL) {
            aR0 = *(const float4*)&Ap[(m0 + lrow) * DMODEL + k0 + 16 + lk];
            aR1 = *(const float4*)&Ap[(m0 + lrow) * DMODEL + k0 + 16 + lk + 4];
            wR0 = *(const float4*)&W[(n0 + lrow) * DMODEL + k0 + 16 + lk];
            wR1 = *(const float4*)&W[(n0 + lrow) * DMODEL + k0 + 16 + lk + 4];
        }

        unsigned ah[2][4], al[2][4];
#pragma unroll
        for (int mf = 0; mf < 2; mf++) {
            int r0 = (wm << 5) + (mf << 4) + g;
            ah[mf][0] = sm.Ah[r0][tg];     ah[mf][1] = sm.Ah[r0 + 8][tg];
            ah[mf][2] = sm.Ah[r0][tg + 4]; ah[mf][3] = sm.Ah[r0 + 8][tg + 4];
            al[mf][0] = sm.Al[r0][tg];     al[mf][1] = sm.Al[r0 + 8][tg];
            al[mf][2] = sm.Al[r0][tg + 4]; al[mf][3] = sm.Al[r0 + 8][tg + 4];
        }
#pragma unroll
        for (int nf = 0; nf < 8; nf++) {
            int nr = (wn << 6) + (nf << 3) + g;
            unsigned bh[2], bl[2];
            bh[0] = sm.Wh[nr][tg]; bh[1] = sm.Wh[nr][tg + 4];
            bl[0] = sm.Wl[nr][tg]; bl[1] = sm.Wl[nr][tg + 4];
#pragma unroll
            for (int mf = 0; mf < 2; mf++) {
                mma_bf16(acc[mf][nf], al[mf], bh);   // lo*hi
                mma_bf16(acc[mf][nf], ah[mf], bl);   // hi*lo
                mma_bf16(acc[mf][nf], ah[mf], bh);   // hi*hi
            }
        }
    }
}

// ---- fused Q/K/V projections: blockIdx.z selects the GEMM.
// Outputs are rounded to tf32 so the attention kernel needs NO cvt. ----
__global__ __launch_bounds__(256, 2) void gemm_qkv_kernel(
    const float* __restrict__ query, const float* __restrict__ key,
    const float* __restrict__ value, const float* __restrict__ Wq,
    const float* __restrict__ Wk, const float* __restrict__ Wv)
{
    const int z = blockIdx.z;
    const float* Ap = (z == 0) ? query : ((z == 1) ? key : value);
    const float* W  = (z == 0) ? Wq    : ((z == 1) ? Wk  : Wv);
    float* outp     = (z == 0) ? g_Q   : ((z == 1) ? g_K : g_V);

    const int m0 = blockIdx.y << 7;
    const int n0 = blockIdx.x << 7;

    float acc[2][8][4];
    gemm_core(Ap, W, m0, n0, acc);

    const int tid  = threadIdx.x;
    const int warp = tid >> 5;
    const int lane = tid & 31;
    const int g    = lane >> 2;
    const int tg   = lane & 3;
    const int wm   = warp >> 1;
    const int wn   = warp & 1;

#pragma unroll
    for (int mf = 0; mf < 2; mf++) {
        int m = m0 + (wm << 5) + (mf << 4) + g;
        int bb0 = m >> 11;
        int s   = m & 2047;
        int mb1 = m + 8;
        int bb1 = mb1 >> 11;
        int s1  = mb1 & 2047;
#pragma unroll
        for (int nf = 0; nf < 8; nf++) {
            int n = n0 + (wn << 6) + (nf << 3) + (tg << 1);
            int h = n >> 6;
            int d = n & 63;
            float2 w0, w1;
            w0.x = __uint_as_float(f2tf32(acc[mf][nf][0]));
            w0.y = __uint_as_float(f2tf32(acc[mf][nf][1]));
            w1.x = __uint_as_float(f2tf32(acc[mf][nf][2]));
            w1.y = __uint_as_float(f2tf32(acc[mf][nf][3]));
            *(float2*)&outp[(((bb0 << 4) + h) * SEQ + s) * DK + d] = w0;
            *(float2*)&outp[(((bb1 << 4) + h) * SEQ + s1) * DK + d] = w1;
        }
    }
}

// ---- output projection: C = g_O @ Wout^T + bias ----
__global__ __launch_bounds__(256, 2) void gemm_out_kernel(
    const float* __restrict__ Wout, const float* __restrict__ bias,
    float* __restrict__ outFlat)
{
    const int m0 = blockIdx.y << 7;
    const int n0 = blockIdx.x << 7;

    float acc[2][8][4];
    gemm_core(g_O, Wout, m0, n0, acc);

    const int tid  = threadIdx.x;
    const int warp = tid >> 5;
    const int lane = tid & 31;
    const int g    = lane >> 2;
    const int tg   = lane & 3;
    const int wm   = warp >> 1;
    const int wn   = warp & 1;

#pragma unroll
    for (int mf = 0; mf < 2; mf++) {
        int r0 = m0 + (wm << 5) + (mf << 4) + g;
#pragma unroll
        for (int nf = 0; nf < 8; nf++) {
            int n = n0 + (wn << 6) + (nf << 3) + (tg << 1);
            float2 bi = *(const float2*)&bias[n];
            float2 w0, w1;
            w0.x = acc[mf][nf][0] + bi.x; w0.y = acc[mf][nf][1] + bi.y;
            w1.x = acc[mf][nf][2] + bi.x; w1.y = acc[mf][nf][3] + bi.y;
            *(float2*)&outFlat[r0 * DMODEL + n] = w0;
            *(float2*)&outFlat[(r0 + 8) * DMODEL + n] = w1;
        }
    }
}

// ---------------------------------------------------------------------------
// Flash attention, tf32 mma.sync, cp.async double-buffered K/V.
// g_Q/g_K/g_V hold tf32-rounded floats -> NO cvt needed in inner loops.
// (Unchanged from R6.)
// ---------------------------------------------------------------------------
#define AQP_ST 72
#define AK_ST  68
#define AV_ST  72
#define KBUF_W (64 * AK_ST)
#define VBUF_W (64 * AV_ST)
#define ATTN_SMEM_BYTES ((128 * AQP_ST + 2 * KBUF_W + 2 * VBUF_W) * 4)  // 108544

__global__ __launch_bounds__(256, 2) void attn_mma_kernel(
    const unsigned char* __restrict__ mask, const int* __restrict__ is_causal_p)
{
    extern __shared__ unsigned smu[];
    unsigned* QPs  = smu;                       // [128][72]
    unsigned* Kbuf = smu + 128 * AQP_ST;        // 2 x [64][68]
    unsigned* Vbuf = Kbuf + 2 * KBUF_W;         // 2 x [64][72]

    const int bh = blockIdx.y;
    const int qt = gridDim.x - 1 - blockIdx.x;  // heavy (large-ntiles) CTAs first
    const int b  = bh >> 4;
    const int h  = bh & 15;
    const int causal = is_causal_p[0];
    const int q0 = qt << 7;

    const int tid  = threadIdx.x;
    const int warp = tid >> 5;
    const int lane = tid & 31;
    const int g    = lane >> 2;
    const int tg   = lane & 3;

    const float* Qg = g_Q + ((size_t)bh * SEQ + q0) * DK;
    const float* Kg = g_K + (size_t)bh * SEQ * DK;
    const float* Vg = g_V + (size_t)bh * SEQ * DK;

    const int lrow = tid >> 4;              // 0..15
    const int lc4  = (tid & 15) << 2;       // 0,4,..,60

    // ---- Load Q tile (already tf32-valued): plain copy ----
#pragma unroll
    for (int it = 0; it < 8; it++) {
        int r = lrow + (it << 4);
        *(uint4*)&QPs[r * AQP_ST + lc4] = *(const uint4*)&Qg[r * DK + lc4];
    }

    // ---- cp.async tile 0 into buffer 0 ----
#pragma unroll
    for (int it = 0; it < 4; it++) {
        int r = lrow + (it << 4);
        unsigned kd = (unsigned)__cvta_generic_to_shared(&Kbuf[r * AK_ST + lc4]);
        CP_ASYNC16(kd, &Kg[r * DK + lc4]);
        unsigned vd = (unsigned)__cvta_generic_to_shared(&Vbuf[r * AV_ST + lc4]);
        CP_ASYNC16(vd, &Vg[r * DK + lc4]);
    }
    CP_COMMIT();
    __syncthreads();

    // ---- Q fragments ----
    const int r0 = (warp << 4) + g;
    const int r1 = r0 + 8;
    unsigned qf[8][4];
#pragma unroll
    for (int ks = 0; ks < 8; ks++) {
        int k = (ks << 3) + tg;
        qf[ks][0] = QPs[r0 * AQP_ST + k];
        qf[ks][1] = QPs[r1 * AQP_ST + k];
        qf[ks][2] = QPs[r0 * AQP_ST + k + 4];
        qf[ks][3] = QPs[r1 * AQP_ST + k + 4];
    }

    const int gr0 = q0 + r0;
    const int gr1 = q0 + r1;
    const unsigned char* mrow0 = mask + (size_t)b * SEQ * SEQ + (size_t)gr0 * SEQ;
    const unsigned char* mrow1 = mask + (size_t)b * SEQ * SEQ + (size_t)gr1 * SEQ;

    float m0 = -1e30f, m1 = -1e30f, l0 = 0.f, l1 = 0.f;
    float of[8][4];
#pragma unroll
    for (int nf = 0; nf < 8; nf++)
#pragma unroll
        for (int j = 0; j < 4; j++) of[nf][j] = 0.f;

    const int ntiles = causal ? (2 * qt + 2) : (SEQ / 64);
    const float scale = 0.125f;

    for (int t = 0; t < ntiles; t++) {
        const int k0 = t << 6;
        if (t > 0) __syncthreads();

        if (t + 1 < ntiles) {
            const int nb = (t + 1) & 1;
            const float* Kt = Kg + ((t + 1) << 6) * DK;
            const float* Vt = Vg + ((t + 1) << 6) * DK;
            unsigned* Kd = Kbuf + nb * KBUF_W;
            unsigned* Vd = Vbuf + nb * VBUF_W;
#pragma unroll
            for (int it = 0; it < 4; it++) {
                int r = lrow + (it << 4);
                unsigned kd = (unsigned)__cvta_generic_to_shared(&Kd[r * AK_ST + lc4]);
                CP_ASYNC16(kd, &Kt[r * DK + lc4]);
                unsigned vd = (unsigned)__cvta_generic_to_shared(&Vd[r * AV_ST + lc4]);
                CP_ASYNC16(vd, &Vt[r * DK + lc4]);
            }
        }
        CP_COMMIT();
        CP_WAIT1();
        __syncthreads();

        const unsigned* Kb = Kbuf + (t & 1) * KBUF_W;
        const unsigned* Vb = Vbuf + (t & 1) * VBUF_W;

        // ---- mask prefetch ----
        uchar2 mA[8], mB[8];
#pragma unroll
        for (int nf = 0; nf < 8; nf++) {
            int col = k0 + (nf << 3) + (tg << 1);
            mA[nf] = *(const uchar2*)(mrow0 + col);
            mB[nf] = *(const uchar2*)(mrow1 + col);
        }

        // ---- S = Q @ K^T (no cvt: bits already tf32) ----
        float s[8][4];
#pragma unroll
        for (int nf = 0; nf < 8; nf++)
#pragma unroll
            for (int j = 0; j < 4; j++) s[nf][j] = 0.f;

#pragma unroll
        for (int nf = 0; nf < 8; nf++) {
            int nrow = (nf << 3) + g;
#pragma unroll
            for (int ks = 0; ks < 8; ks++) {
                int k = (ks << 3) + tg;
                unsigned bb[2];
                bb[0] = Kb[nrow * AK_ST + k];
                bb[1] = Kb[nrow * AK_ST + k + 4];
                mma_tf32(s[nf], qf[ks], bb);
            }
        }

        // ---- scale + mask ----
#pragma unroll
        for (int nf = 0; nf < 8; nf++) {
            int col = k0 + (nf << 3) + (tg << 1);
            bool d00 = mA[nf].x || (causal && (col     > gr0));
            bool d01 = mA[nf].y || (causal && (col + 1 > gr0));
            bool d10 = mB[nf].x || (causal && (col     > gr1));
            bool d11 = mB[nf].y || (causal && (col + 1 > gr1));
            s[nf][0] = d00 ? -1e30f : s[nf][0] * scale;
            s[nf][1] = d01 ? -1e30f : s[nf][1] * scale;
            s[nf][2] = d10 ? -1e30f : s[nf][2] * scale;
            s[nf][3] = d11 ? -1e30f : s[nf][3] * scale;
        }

        // ---- online softmax ----
        float mx0 = -1e30f, mx1 = -1e30f;
#pragma unroll
        for (int nf = 0; nf < 8; nf++) {
            mx0 = fmaxf(mx0, fmaxf(s[nf][0], s[nf][1]));
            mx1 = fmaxf(mx1, fmaxf(s[nf][2], s[nf][3]));
        }
        mx0 = fmaxf(mx0, __shfl_xor_sync(0xffffffffu, mx0, 1));
        mx0 = fmaxf(mx0, __shfl_xor_sync(0xffffffffu, mx0, 2));
        mx1 = fmaxf(mx1, __shfl_xor_sync(0xffffffffu, mx1, 1));
        mx1 = fmaxf(mx1, __shfl_xor_sync(0xffffffffu, mx1, 2));
        float m0n = fmaxf(m0, mx0);
        float m1n = fmaxf(m1, mx1);
        float sf0 = __expf(m0 - m0n);
        float sf1 = __expf(m1 - m1n);
        float rs0 = 0.f, rs1 = 0.f;
#pragma unroll
        for (int nf = 0; nf < 8; nf++) {
            float p0 = __expf(s[nf][0] - m0n);
            float p1 = __expf(s[nf][1] - m0n);
            float p2 = __expf(s[nf][2] - m1n);
            float p3 = __expf(s[nf][3] - m1n);
            s[nf][0] = p0; s[nf][1] = p1; s[nf][2] = p2; s[nf][3] = p3;
            rs0 += p0 + p1;
            rs1 += p2 + p3;
        }
        rs0 += __shfl_xor_sync(0xffffffffu, rs0, 1);
        rs0 += __shfl_xor_sync(0xffffffffu, rs0, 2);
        rs1 += __shfl_xor_sync(0xffffffffu, rs1, 1);
        rs1 += __shfl_xor_sync(0xffffffffu, rs1, 2);
        l0 = l0 * sf0 + rs0;
        l1 = l1 * sf1 + rs1;
        m0 = m0n; m1 = m1n;
#pragma unroll
        for (int nf = 0; nf < 8; nf++) {
            of[nf][0] *= sf0; of[nf][1] *= sf0;
            of[nf][2] *= sf1; of[nf][3] *= sf1;
        }

        // ---- write P (tf32) to warp-local rows of QPs ----
#pragma unroll
        for (int nf = 0; nf < 8; nf++) {
            int c = (nf << 3) + (tg << 1);
            uint2 p0; p0.x = f2tf32(s[nf][0]); p0.y = f2tf32(s[nf][1]);
            uint2 p1; p1.x = f2tf32(s[nf][2]); p1.y = f2tf32(s[nf][3]);
            *(uint2*)&QPs[r0 * AQP_ST + c] = p0;
            *(uint2*)&QPs[r1 * AQP_ST + c] = p1;
        }
        __syncwarp();

        // ---- O += P @ V ----
#pragma unroll
        for (int ks = 0; ks < 8; ks++) {
            unsigned a[4];
            int k = (ks << 3) + tg;
            a[0] = QPs[r0 * AQP_ST + k];
            a[1] = QPs[r1 * AQP_ST + k];
            a[2] = QPs[r0 * AQP_ST + k + 4];
            a[3] = QPs[r1 * AQP_ST + k + 4];
#pragma unroll
            for (int nf = 0; nf < 8; nf++) {
                int n = (nf << 3) + g;
                unsigned bb[2];
                bb[0] = Vb[((ks << 3) + tg) * AV_ST + n];
                bb[1] = Vb[((ks << 3) + tg + 4) * AV_ST + n];
                mma_tf32(of[nf], a, bb);
            }
        }
        __syncwarp();
    }

    // ---- epilogue ----
    float inv0 = (m0 > -1e29f && l0 > 0.f) ? (1.f / l0) : 0.f;
    float inv1 = (m1 > -1e29f && l1 > 0.f) ? (1.f / l1) : 0.f;
    float* Og0 = g_O + ((size_t)b * SEQ + gr0) * DMODEL + (h << 6);
    float* Og1 = g_O + ((size_t)b * SEQ + gr1) * DMODEL + (h << 6);
#pragma unroll
    for (int nf = 0; nf < 8; nf++) {
        int c = (nf << 3) + (tg << 1);
        float2 w0; w0.x = of[nf][0] * inv0; w0.y = of[nf][1] * inv0;
        float2 w1; w1.x = of[nf][2] * inv1; w1.y = of[nf][3] * inv1;
        *(float2*)&Og0[c] = w0;
        *(float2*)&Og1[c] = w1;
    }
}

// ---------------------------------------------------------------------------
extern "C" void kernel_launch(void* const* d_in, const int* in_sizes, int n_in,
                              void* d_out, int out_size)
{
    const float* query = (const float*)d_in[0];
    const float* key   = (const float*)d_in[1];
    const float* value = (const float*)d_in[2];
    const unsigned char* mask = (const unsigned char*)d_in[3];
    const float* Wq    = (const float*)d_in[4];
    const float* Wk    = (const float*)d_in[5];
    const float* Wv    = (const float*)d_in[6];
    const float* Wout  = (const float*)d_in[7];
    const float* b_out = (const float*)d_in[8];
    const int* is_causal = (const int*)d_in[9];
    float* out = (float*)d_out;

    cudaFuncSetAttribute(attn_mma_kernel,
                         cudaFuncAttributeMaxDynamicSharedMemorySize, ATTN_SMEM_BYTES);

    dim3 qkvgrid(DMODEL / 128, MROWS / 128, 3);   // (8, 32, 3)
    gemm_qkv_kernel<<<qkvgrid, 256>>>(query, key, value, Wq, Wk, Wv);

    dim3 agrid(SEQ / 128, BATCH * NHEAD);         // (16, 32)
    attn_mma_kernel<<<agrid, 256, ATTN_SMEM_BYTES>>>(mask, is_causal);

    dim3 ogrid(DMODEL / 128, MROWS / 128);        // (8, 32)
    gemm_out_kernel<<<ogrid, 256>>>(Wout, b_out, out);
}